// round 1
// baseline (speedup 1.0000x reference)
#include <cuda_runtime.h>

#define SEQ 4096
#define DM  1024
#define NH  16
#define HD  64

// Scratch buffers (allocation inside kernel_launch is forbidden).
static __device__ float g_Q [SEQ * DM];
static __device__ float g_K [SEQ * DM];
static __device__ float g_V [SEQ * DM];
static __device__ float g_AO[SEQ * DM];

// ---------------------------------------------------------------------------
// GEMM: C[M,N] = A[M,K] @ W[N,K]^T + bias[N]
// 128x128 block tile, K-tile 16, 256 threads, 8x8 per-thread micro-tile,
// register prefetch of the next global tile.
// ---------------------------------------------------------------------------
__global__ void __launch_bounds__(256, 2)
gemm_bias(const float* __restrict__ A, const float* __restrict__ W,
          const float* __restrict__ bias, float* __restrict__ C,
          int M, int N, int K)
{
    __shared__ float As[16][132];   // [k][m], padded
    __shared__ float Ws[16][132];   // [k][n], padded

    const int tid = threadIdx.x;
    const int tm  = tid >> 4;       // 0..15
    const int tn  = tid & 15;       // 0..15
    const int bm  = blockIdx.y;
    const int bn  = blockIdx.x;

    // Each thread loads 2 float4 per operand per K-tile (128x16 = 512 float4).
    const int i0  = tid * 2;
    const int ar0 = i0 >> 2,       ac0 = (i0 & 3) << 2;
    const int ar1 = (i0 + 1) >> 2, ac1 = ((i0 + 1) & 3) << 2;

    const float* Ab = A + (size_t)bm * 128 * K;
    const float* Wb = W + (size_t)bn * 128 * K;

    float acc[8][8];
    #pragma unroll
    for (int i = 0; i < 8; i++)
        #pragma unroll
        for (int j = 0; j < 8; j++) acc[i][j] = 0.f;

    const int NK = K >> 4;

    // Preload tile 0
    float4 a0 = *(const float4*)(Ab + (size_t)ar0 * K + ac0);
    float4 a1 = *(const float4*)(Ab + (size_t)ar1 * K + ac1);
    float4 w0 = *(const float4*)(Wb + (size_t)ar0 * K + ac0);
    float4 w1 = *(const float4*)(Wb + (size_t)ar1 * K + ac1);
    As[ac0+0][ar0] = a0.x; As[ac0+1][ar0] = a0.y; As[ac0+2][ar0] = a0.z; As[ac0+3][ar0] = a0.w;
    As[ac1+0][ar1] = a1.x; As[ac1+1][ar1] = a1.y; As[ac1+2][ar1] = a1.z; As[ac1+3][ar1] = a1.w;
    Ws[ac0+0][ar0] = w0.x; Ws[ac0+1][ar0] = w0.y; Ws[ac0+2][ar0] = w0.z; Ws[ac0+3][ar0] = w0.w;
    Ws[ac1+0][ar1] = w1.x; Ws[ac1+1][ar1] = w1.y; Ws[ac1+2][ar1] = w1.z; Ws[ac1+3][ar1] = w1.w;
    __syncthreads();

    for (int kt = 0; kt < NK; kt++) {
        const bool more = (kt + 1 < NK);
        float4 na0, na1, nw0, nw1;
        if (more) {
            const float* Ap = Ab + (kt + 1) * 16;
            const float* Wp = Wb + (kt + 1) * 16;
            na0 = *(const float4*)(Ap + (size_t)ar0 * K + ac0);
            na1 = *(const float4*)(Ap + (size_t)ar1 * K + ac1);
            nw0 = *(const float4*)(Wp + (size_t)ar0 * K + ac0);
            nw1 = *(const float4*)(Wp + (size_t)ar1 * K + ac1);
        }

        #pragma unroll
        for (int kk = 0; kk < 16; kk++) {
            float4 av0 = *(const float4*)&As[kk][tm * 8];
            float4 av1 = *(const float4*)&As[kk][tm * 8 + 4];
            float4 bv0 = *(const float4*)&Ws[kk][tn * 8];
            float4 bv1 = *(const float4*)&Ws[kk][tn * 8 + 4];
            float a[8] = {av0.x, av0.y, av0.z, av0.w, av1.x, av1.y, av1.z, av1.w};
            float b[8] = {bv0.x, bv0.y, bv0.z, bv0.w, bv1.x, bv1.y, bv1.z, bv1.w};
            #pragma unroll
            for (int i = 0; i < 8; i++)
                #pragma unroll
                for (int j = 0; j < 8; j++)
                    acc[i][j] = fmaf(a[i], b[j], acc[i][j]);
        }
        __syncthreads();
        if (more) {
            As[ac0+0][ar0] = na0.x; As[ac0+1][ar0] = na0.y; As[ac0+2][ar0] = na0.z; As[ac0+3][ar0] = na0.w;
            As[ac1+0][ar1] = na1.x; As[ac1+1][ar1] = na1.y; As[ac1+2][ar1] = na1.z; As[ac1+3][ar1] = na1.w;
            Ws[ac0+0][ar0] = nw0.x; Ws[ac0+1][ar0] = nw0.y; Ws[ac0+2][ar0] = nw0.z; Ws[ac0+3][ar0] = nw0.w;
            Ws[ac1+0][ar1] = nw1.x; Ws[ac1+1][ar1] = nw1.y; Ws[ac1+2][ar1] = nw1.z; Ws[ac1+3][ar1] = nw1.w;
        }
        __syncthreads();
    }

    // Epilogue: add bias, store 2 float4 per row of the 8x8 micro-tile.
    const int row0 = bm * 128 + tm * 8;
    const int col0 = bn * 128 + tn * 8;
    float bb[8];
    #pragma unroll
    for (int j = 0; j < 8; j++) bb[j] = bias[col0 + j];
    #pragma unroll
    for (int i = 0; i < 8; i++) {
        float4 o0 = make_float4(acc[i][0] + bb[0], acc[i][1] + bb[1],
                                acc[i][2] + bb[2], acc[i][3] + bb[3]);
        float4 o1 = make_float4(acc[i][4] + bb[4], acc[i][5] + bb[5],
                                acc[i][6] + bb[6], acc[i][7] + bb[7]);
        *(float4*)&C[(size_t)(row0 + i) * N + col0]     = o0;
        *(float4*)&C[(size_t)(row0 + i) * N + col0 + 4] = o1;
    }
}

// ---------------------------------------------------------------------------
// Causal flash attention, fp32. One CTA = (head, 64-query tile).
// BQ = BK = 64, 256 threads, 4x4 per-thread micro-tiles for QK^T and PV.
// ---------------------------------------------------------------------------
#define QP 68   // padded pitch for [d][q]-major / [k][q]-major tiles
#define FLASH_SMEM ((64 * QP * 3 + 64 * 64 + 3 * 64) * 4)

__global__ void __launch_bounds__(256)
flash_attn()
{
    extern __shared__ float smf[];
    float* Qs  = smf;                 // [d][q], pitch QP, pre-scaled by 1/8
    float* Ks  = Qs + 64 * QP;        // [d][k], pitch QP
    float* Vs  = Ks + 64 * QP;        // [k][v], pitch 64
    float* Ss  = Vs + 64 * 64;        // [k][q], pitch QP (scores, then probs)
    float* m_s = Ss + 64 * QP;        // row running max
    float* l_s = m_s + 64;            // row running sum
    float* a_s = l_s + 64;            // row alpha

    const int tid = threadIdx.x;
    const int tm  = tid >> 4;         // q micro-row group 0..15
    const int tn  = tid & 15;         // k/v micro-col group 0..15
    const int h   = blockIdx.y;
    const int qt  = (int)gridDim.x - 1 - (int)blockIdx.x;  // longest-work first
    const int q0  = qt * 64;
    const size_t hoff = (size_t)h * HD;

    // Load Q tile transposed to [d][q], fused scale by 1/sqrt(DK)=0.125
    #pragma unroll
    for (int s = 0; s < 4; s++) {
        int idx = tid + 256 * s;
        int r = idx >> 4;
        int c = (idx & 15) << 2;
        float4 q4 = *(const float4*)&g_Q[(size_t)(q0 + r) * DM + hoff + c];
        Qs[(c + 0) * QP + r] = q4.x * 0.125f;
        Qs[(c + 1) * QP + r] = q4.y * 0.125f;
        Qs[(c + 2) * QP + r] = q4.z * 0.125f;
        Qs[(c + 3) * QP + r] = q4.w * 0.125f;
    }
    if (tid < 64) { m_s[tid] = -1e30f; l_s[tid] = 0.f; }

    float o[4][4] = {};

    for (int kt = 0; kt <= qt; kt++) {
        const int k0 = kt * 64;
        __syncthreads();   // previous PV / epilogue reads done before overwrite

        // Load K (transposed to [d][k]) and V ([k][v]) tiles
        #pragma unroll
        for (int s = 0; s < 4; s++) {
            int idx = tid + 256 * s;
            int r = idx >> 4;
            int c = (idx & 15) << 2;
            float4 k4 = *(const float4*)&g_K[(size_t)(k0 + r) * DM + hoff + c];
            Ks[(c + 0) * QP + r] = k4.x;
            Ks[(c + 1) * QP + r] = k4.y;
            Ks[(c + 2) * QP + r] = k4.z;
            Ks[(c + 3) * QP + r] = k4.w;
            float4 v4 = *(const float4*)&g_V[(size_t)(k0 + r) * DM + hoff + c];
            *(float4*)&Vs[r * 64 + c] = v4;
        }
        __syncthreads();

        // S = (Q/8) K^T   (4x4 per thread)
        float sacc[4][4] = {};
        #pragma unroll 8
        for (int d = 0; d < 64; d++) {
            float4 qa = *(const float4*)&Qs[d * QP + (tm << 2)];
            float4 kb = *(const float4*)&Ks[d * QP + (tn << 2)];
            float aq[4] = {qa.x, qa.y, qa.z, qa.w};
            float bk[4] = {kb.x, kb.y, kb.z, kb.w};
            #pragma unroll
            for (int i = 0; i < 4; i++)
                #pragma unroll
                for (int j = 0; j < 4; j++)
                    sacc[i][j] = fmaf(aq[i], bk[j], sacc[i][j]);
        }

        // Causal mask only needed on the diagonal tile (k0 == q0 there)
        if (kt == qt) {
            #pragma unroll
            for (int i = 0; i < 4; i++)
                #pragma unroll
                for (int j = 0; j < 4; j++)
                    if ((tn << 2) + j > (tm << 2) + i) sacc[i][j] = -1e30f;
        }

        // Store scores transposed: Ss[k][q]
        #pragma unroll
        for (int j = 0; j < 4; j++) {
            *(float4*)&Ss[((tn << 2) + j) * QP + (tm << 2)] =
                make_float4(sacc[0][j], sacc[1][j], sacc[2][j], sacc[3][j]);
        }
        __syncthreads();

        // Online softmax: one thread per query row
        if (tid < 64) {
            float mi = m_s[tid];
            float mx = mi;
            #pragma unroll 8
            for (int j = 0; j < 64; j++) mx = fmaxf(mx, Ss[j * QP + tid]);
            float alpha = __expf(mi - mx);
            float sum = 0.f;
            #pragma unroll 8
            for (int j = 0; j < 64; j++) {
                float p = __expf(Ss[j * QP + tid] - mx);
                Ss[j * QP + tid] = p;
                sum += p;
            }
            m_s[tid] = mx;
            l_s[tid] = l_s[tid] * alpha + sum;
            a_s[tid] = alpha;
        }
        __syncthreads();

        // Rescale running O, then O += P @ V
        {
            float al[4];
            #pragma unroll
            for (int i = 0; i < 4; i++) al[i] = a_s[(tm << 2) + i];
            #pragma unroll
            for (int i = 0; i < 4; i++)
                #pragma unroll
                for (int j = 0; j < 4; j++) o[i][j] *= al[i];
        }
        #pragma unroll 4
        for (int j = 0; j < 64; j++) {
            float4 pa = *(const float4*)&Ss[j * QP + (tm << 2)];
            float4 vb = *(const float4*)&Vs[j * 64 + (tn << 2)];
            float pp[4] = {pa.x, pa.y, pa.z, pa.w};
            float vv[4] = {vb.x, vb.y, vb.z, vb.w};
            #pragma unroll
            for (int i = 0; i < 4; i++)
                #pragma unroll
                for (int v = 0; v < 4; v++)
                    o[i][v] = fmaf(pp[i], vv[v], o[i][v]);
        }
    }

    // Epilogue: normalize and write [s, h*DV + v]
    #pragma unroll
    for (int i = 0; i < 4; i++) {
        float inv = 1.f / l_s[(tm << 2) + i];
        *(float4*)&g_AO[(size_t)(q0 + (tm << 2) + i) * DM + hoff + (tn << 2)] =
            make_float4(o[i][0] * inv, o[i][1] * inv, o[i][2] * inv, o[i][3] * inv);
    }
}

// ---------------------------------------------------------------------------
extern "C" void kernel_launch(void* const* d_in, const int* in_sizes, int n_in,
                              void* d_out, int out_size)
{
    const float* queries = (const float*)d_in[0];
    const float* keys    = (const float*)d_in[1];
    const float* values  = (const float*)d_in[2];
    const float* Wq      = (const float*)d_in[3];
    const float* bq      = (const float*)d_in[4];
    const float* Wk      = (const float*)d_in[5];
    const float* bk      = (const float*)d_in[6];
    const float* Wv      = (const float*)d_in[7];
    const float* bv      = (const float*)d_in[8];
    const float* Wo      = (const float*)d_in[9];
    const float* bo      = (const float*)d_in[10];
    float* out = (float*)d_out;

    float *Qp, *Kp, *Vp, *AOp;
    cudaGetSymbolAddress((void**)&Qp,  g_Q);
    cudaGetSymbolAddress((void**)&Kp,  g_K);
    cudaGetSymbolAddress((void**)&Vp,  g_V);
    cudaGetSymbolAddress((void**)&AOp, g_AO);

    cudaFuncSetAttribute(flash_attn, cudaFuncAttributeMaxDynamicSharedMemorySize,
                         FLASH_SMEM);

    dim3 ggrid(DM / 128, SEQ / 128);   // (8, 32)

    gemm_bias<<<ggrid, 256>>>(queries, Wq, bq, Qp, SEQ, DM, DM);
    gemm_bias<<<ggrid, 256>>>(keys,    Wk, bk, Kp, SEQ, DM, DM);
    gemm_bias<<<ggrid, 256>>>(values,  Wv, bv, Vp, SEQ, DM, DM);

    flash_attn<<<dim3(SEQ / 64, NH), 256, FLASH_SMEM>>>();

    gemm_bias<<<ggrid, 256>>>(AOp, Wo, bo, out, SEQ, DM, DM);
}